// round 11
// baseline (speedup 1.0000x reference)
#include <cuda_runtime.h>
#include <math.h>

#define FULL_MASK 0xFFFFFFFFu
typedef unsigned long long u64;

// ---------- f32x2 packed helpers (FFMA2 is PTX-only; ptxas won't auto-fuse) ----------
__device__ __forceinline__ u64 f2pack(float lo, float hi) {
    u64 r; asm("mov.b64 %0, {%1, %2};" : "=l"(r) : "f"(lo), "f"(hi)); return r;
}
__device__ __forceinline__ void f2unpack(u64 v, float& lo, float& hi) {
    asm("mov.b64 {%0, %1}, %2;" : "=f"(lo), "=f"(hi) : "l"(v));
}
__device__ __forceinline__ u64 ffma2(u64 a, u64 b, u64 c) {
    u64 d; asm("fma.rn.f32x2 %0, %1, %2, %3;" : "=l"(d) : "l"(a), "l"(b), "l"(c)); return d;
}
__device__ __forceinline__ u64 fmul2(u64 a, u64 b) {
    u64 d; asm("mul.rn.f32x2 %0, %1, %2;" : "=l"(d) : "l"(a), "l"(b)); return d;
}

// ---------- 4-qubit circuit pieces (identical math to passing R6 kernel) ----------
template<int STRIDE>
__device__ __forceinline__ void apply_ry_s(float st[16], float c, float s) {
#pragma unroll
    for (int base = 0; base < 16; base += 2 * STRIDE) {
#pragma unroll
        for (int i = 0; i < STRIDE; i++) {
            float a0 = st[base + i];
            float a1 = st[base + i + STRIDE];
            st[base + i]          = c * a0 - s * a1;
            st[base + i + STRIDE] = s * a0 + c * a1;
        }
    }
}
__device__ __forceinline__ void cnot01(float st[16]) {
#pragma unroll
    for (int i = 0; i < 4; i++) { float t = st[8 + i]; st[8 + i] = st[12 + i]; st[12 + i] = t; }
}
__device__ __forceinline__ void cnot23(float st[16]) {
#pragma unroll
    for (int b = 0; b < 16; b += 4) { float t = st[b + 2]; st[b + 2] = st[b + 3]; st[b + 3] = t; }
}
__device__ __forceinline__ void cnot12(float st[16]) {
#pragma unroll
    for (int q0 = 0; q0 < 2; q0++)
#pragma unroll
        for (int q3 = 0; q3 < 2; q3++) {
            int b = q0 * 8 + 4 + q3;
            float t = st[b]; st[b] = st[b + 2]; st[b + 2] = t;
        }
}

__global__ __launch_bounds__(128, 4)
void dqn_fused_kernel(const float* __restrict__ X,      // [B,512]
                      const float* __restrict__ Wpre,   // [4,512]
                      const float* __restrict__ bpre,   // [4]
                      const float* __restrict__ qp,     // [24]
                      const float* __restrict__ Wpost,  // [200,4]
                      const float* __restrict__ bpost,  // [200]
                      float* __restrict__ out,          // [B,200]
                      int B)
{
    // layer-angle cos/sin (uniform across samples): accurate sincosf, once per block
    __shared__ float lc[24], ls[24], sb[4];
    const int tid = threadIdx.x;
    if (tid < 24) {
        float s, c;
        sincosf(qp[tid] * 0.5f, &s, &c);
        lc[tid] = c; ls[tid] = s;
    }
    if (tid < 4) sb[tid] = bpre[tid];
    __syncthreads();

    const int lane = tid & 31;
    const int warp = tid >> 5;
    const int group = blockIdx.x * 4 + warp;    // one warp per 32 samples
    const int base = group * 32;
    if (base >= B) return;

    // ---- Phase 1: pre = X @ Wpre.T ----
    // lane covers cols {lane*4 + j*128 + 0..3}; W_pre held in regs as f32x2 pairs
    u64 w2[4][8];
#pragma unroll
    for (int q = 0; q < 4; q++)
#pragma unroll
        for (int j = 0; j < 4; j++) {
            float4 wv = *(const float4*)(Wpre + q * 512 + j * 128 + lane * 4);
            w2[q][2 * j]     = f2pack(wv.x, wv.y);
            w2[q][2 * j + 1] = f2pack(wv.z, wv.w);
        }

    float pre0 = 0.f, pre1 = 0.f, pre2 = 0.f, pre3 = 0.f;
    const bool o0 = (lane & 1) != 0;
    const bool o1 = (lane & 2) != 0;
    const bool o2 = (lane & 4) != 0;
    const bool o3 = (lane & 8) != 0;
    const int srcbase = (lane & 3) << 2;   // broadcast source base for batch gather
    const int mybatch = lane >> 2;         // which batch this lane owns

#pragma unroll 2
    for (int b = 0; b < 8; b++) {          // batches of 4 samples
        float a[4][4];                     // [sample-in-batch][q] lane partials
#pragma unroll
        for (int i = 0; i < 4; i++) {
            const float4* row4 = (const float4*)(X + (size_t)(base + b * 4 + i) * 512) + lane;
            u64 acc0, acc1, acc2, acc3;
            {
                float4 xv = __ldcs(row4);
                u64 xlo = f2pack(xv.x, xv.y), xhi = f2pack(xv.z, xv.w);
                acc0 = fmul2(xlo, w2[0][0]); acc0 = ffma2(xhi, w2[0][1], acc0);
                acc1 = fmul2(xlo, w2[1][0]); acc1 = ffma2(xhi, w2[1][1], acc1);
                acc2 = fmul2(xlo, w2[2][0]); acc2 = ffma2(xhi, w2[2][1], acc2);
                acc3 = fmul2(xlo, w2[3][0]); acc3 = ffma2(xhi, w2[3][1], acc3);
            }
#pragma unroll
            for (int j = 1; j < 4; j++) {
                float4 xv = __ldcs(row4 + j * 32);
                u64 xlo = f2pack(xv.x, xv.y), xhi = f2pack(xv.z, xv.w);
                acc0 = ffma2(xlo, w2[0][2 * j], acc0); acc0 = ffma2(xhi, w2[0][2 * j + 1], acc0);
                acc1 = ffma2(xlo, w2[1][2 * j], acc1); acc1 = ffma2(xhi, w2[1][2 * j + 1], acc1);
                acc2 = ffma2(xlo, w2[2][2 * j], acc2); acc2 = ffma2(xhi, w2[2][2 * j + 1], acc2);
                acc3 = ffma2(xlo, w2[3][2 * j], acc3); acc3 = ffma2(xhi, w2[3][2 * j + 1], acc3);
            }
            float lo, hi;
            f2unpack(acc0, lo, hi); a[i][0] = lo + hi;
            f2unpack(acc1, lo, hi); a[i][1] = lo + hi;
            f2unpack(acc2, lo, hi); a[i][2] = lo + hi;
            f2unpack(acc3, lo, hi); a[i][3] = lo + hi;
        }

        // packed butterfly: stages 1-2 fold accumulators (acc idx -> lane bits 0,1)
        float v[4];
#pragma unroll
        for (int i = 0; i < 4; i++) {
            float s01 = o0 ? a[i][0] : a[i][1];
            float r01 = __shfl_xor_sync(FULL_MASK, s01, 1);
            float v01 = (o0 ? a[i][1] : a[i][0]) + r01;
            float s23 = o0 ? a[i][2] : a[i][3];
            float r23 = __shfl_xor_sync(FULL_MASK, s23, 1);
            float v23 = (o0 ? a[i][3] : a[i][2]) + r23;
            float s2  = o1 ? v01 : v23;
            float r2  = __shfl_xor_sync(FULL_MASK, s2, 2);
            v[i] = (o1 ? v23 : v01) + r2;
        }
        // stages 3-4 fold samples (sample idx -> lane bits 2,3), stage 5 reduces bit 4
        float sA = o2 ? v[0] : v[1];
        float rA = __shfl_xor_sync(FULL_MASK, sA, 4);
        float x01 = (o2 ? v[1] : v[0]) + rA;
        float sB = o2 ? v[2] : v[3];
        float rB = __shfl_xor_sync(FULL_MASK, sB, 4);
        float x23 = (o2 ? v[3] : v[2]) + rB;
        float sC = o3 ? x01 : x23;
        float rC = __shfl_xor_sync(FULL_MASK, sC, 8);
        float y  = (o3 ? x23 : x01) + rC;
        y += __shfl_xor_sync(FULL_MASK, y, 16);
        // lane L holds full sum of acc (L&3) for sample 4b + ((L>>2)&3)
        float p0 = __shfl_sync(FULL_MASK, y, srcbase + 0);
        float p1 = __shfl_sync(FULL_MASK, y, srcbase + 1);
        float p2 = __shfl_sync(FULL_MASK, y, srcbase + 2);
        float p3 = __shfl_sync(FULL_MASK, y, srcbase + 3);
        if (mybatch == b) { pre0 = p0; pre1 = p1; pre2 = p2; pre3 = p3; }
    }

    // ---- Phase 2: per-lane 4-qubit circuit (lane == its sample), regs only ----
    float st[16];
#pragma unroll
    for (int i = 0; i < 16; i++) st[i] = 0.25f;
    {
        const float PI_4 = 0.78539816339744830962f;
        float h, c, s;
        h = tanhf(pre0 + sb[0]) * PI_4; c = __cosf(h); s = __sinf(h); apply_ry_s<8>(st, c, s);
        h = tanhf(pre1 + sb[1]) * PI_4; c = __cosf(h); s = __sinf(h); apply_ry_s<4>(st, c, s);
        h = tanhf(pre2 + sb[2]) * PI_4; c = __cosf(h); s = __sinf(h); apply_ry_s<2>(st, c, s);
        h = tanhf(pre3 + sb[3]) * PI_4; c = __cosf(h); s = __sinf(h); apply_ry_s<1>(st, c, s);
    }
#pragma unroll
    for (int k = 0; k < 6; k++) {
        cnot01(st); cnot23(st); cnot12(st);
        apply_ry_s<8>(st, lc[k * 4 + 0], ls[k * 4 + 0]);
        apply_ry_s<4>(st, lc[k * 4 + 1], ls[k * 4 + 1]);
        apply_ry_s<2>(st, lc[k * 4 + 2], ls[k * 4 + 2]);
        apply_ry_s<1>(st, lc[k * 4 + 3], ls[k * 4 + 3]);
    }
    float z0 = 0.f, z1 = 0.f, z2 = 0.f, z3 = 0.f;
#pragma unroll
    for (int i = 0; i < 16; i++) {
        float p = st[i] * st[i];
        z0 += (i & 8) ? -p : p;
        z1 += (i & 4) ? -p : p;
        z2 += (i & 2) ? -p : p;
        z3 += (i & 1) ? -p : p;
    }

    // ---- Phase 3: out = z @ Wpost.T + bpost, f32x2 column-pair FMAs ----
    const int j0 = lane * 4;
    const int j1 = 128 + lane * 4;
    const bool second = (lane < 18);

    u64 c0[4], c1[4], d0[4], d1[4];
    u64 b01, b23, b45 = 0, b67 = 0;
    {
        float4 r0 = *(const float4*)(Wpost + (j0 + 0) * 4);
        float4 r1 = *(const float4*)(Wpost + (j0 + 1) * 4);
        float4 r2 = *(const float4*)(Wpost + (j0 + 2) * 4);
        float4 r3 = *(const float4*)(Wpost + (j0 + 3) * 4);
        c0[0] = f2pack(r0.x, r1.x); c0[1] = f2pack(r0.y, r1.y);
        c0[2] = f2pack(r0.z, r1.z); c0[3] = f2pack(r0.w, r1.w);
        c1[0] = f2pack(r2.x, r3.x); c1[1] = f2pack(r2.y, r3.y);
        c1[2] = f2pack(r2.z, r3.z); c1[3] = f2pack(r2.w, r3.w);
        float4 bp = *(const float4*)(bpost + j0);
        b01 = f2pack(bp.x, bp.y); b23 = f2pack(bp.z, bp.w);
    }
#pragma unroll
    for (int r = 0; r < 4; r++) { d0[r] = 0; d1[r] = 0; }
    if (second) {
        float4 r0 = *(const float4*)(Wpost + (j1 + 0) * 4);
        float4 r1 = *(const float4*)(Wpost + (j1 + 1) * 4);
        float4 r2 = *(const float4*)(Wpost + (j1 + 2) * 4);
        float4 r3 = *(const float4*)(Wpost + (j1 + 3) * 4);
        d0[0] = f2pack(r0.x, r1.x); d0[1] = f2pack(r0.y, r1.y);
        d0[2] = f2pack(r0.z, r1.z); d0[3] = f2pack(r0.w, r1.w);
        d1[0] = f2pack(r2.x, r3.x); d1[1] = f2pack(r2.y, r3.y);
        d1[2] = f2pack(r2.z, r3.z); d1[3] = f2pack(r2.w, r3.w);
        float4 bp = *(const float4*)(bpost + j1);
        b45 = f2pack(bp.x, bp.y); b67 = f2pack(bp.z, bp.w);
    }

#pragma unroll 4
    for (int s = 0; s < 32; s++) {
        float a0 = __shfl_sync(FULL_MASK, z0, s);
        float a1 = __shfl_sync(FULL_MASK, z1, s);
        float a2 = __shfl_sync(FULL_MASK, z2, s);
        float a3 = __shfl_sync(FULL_MASK, z3, s);
        u64 aa0 = f2pack(a0, a0), aa1 = f2pack(a1, a1);
        u64 aa2 = f2pack(a2, a2), aa3 = f2pack(a3, a3);
        float* orow = out + (size_t)(base + s) * 200;

        u64 r01 = ffma2(aa0, c0[0], b01);
        r01 = ffma2(aa1, c0[1], r01); r01 = ffma2(aa2, c0[2], r01); r01 = ffma2(aa3, c0[3], r01);
        u64 r23 = ffma2(aa0, c1[0], b23);
        r23 = ffma2(aa1, c1[1], r23); r23 = ffma2(aa2, c1[2], r23); r23 = ffma2(aa3, c1[3], r23);
        float4 o;
        f2unpack(r01, o.x, o.y); f2unpack(r23, o.z, o.w);
        __stcs((float4*)(orow + j0), o);

        if (second) {
            u64 r45 = ffma2(aa0, d0[0], b45);
            r45 = ffma2(aa1, d0[1], r45); r45 = ffma2(aa2, d0[2], r45); r45 = ffma2(aa3, d0[3], r45);
            u64 r67 = ffma2(aa0, d1[0], b67);
            r67 = ffma2(aa1, d1[1], r67); r67 = ffma2(aa2, d1[2], r67); r67 = ffma2(aa3, d1[3], r67);
            float4 p;
            f2unpack(r45, p.x, p.y); f2unpack(r67, p.z, p.w);
            __stcs((float4*)(orow + j1), p);
        }
    }
}

extern "C" void kernel_launch(void* const* d_in, const int* in_sizes, int n_in,
                              void* d_out, int out_size)
{
    const float* X     = (const float*)d_in[0];
    const float* Wpre  = (const float*)d_in[1];
    const float* bpre  = (const float*)d_in[2];
    const float* qp    = (const float*)d_in[3];
    const float* Wpost = (const float*)d_in[4];
    const float* bpost = (const float*)d_in[5];
    float* out = (float*)d_out;

    int B = in_sizes[0] / 512;            // 65536
    int groups = (B + 31) / 32;           // warps (one per 32 samples)
    int blocks = (groups + 3) / 4;        // 4 warps (128 threads) per block -> 512 blocks

    dqn_fused_kernel<<<blocks, 128>>>(X, Wpre, bpre, qp, Wpost, bpost, out, B);
}

// round 14
// speedup vs baseline: 1.1048x; 1.1048x over previous
#include <cuda_runtime.h>
#include <math.h>

#define FULL_MASK 0xFFFFFFFFu
typedef unsigned long long u64;

// ---------- f32x2 packed helpers (FFMA2 is PTX-only; ptxas won't auto-fuse) ----------
__device__ __forceinline__ u64 f2pack(float lo, float hi) {
    u64 r; asm("mov.b64 %0, {%1, %2};" : "=l"(r) : "f"(lo), "f"(hi)); return r;
}
__device__ __forceinline__ void f2unpack(u64 v, float& lo, float& hi) {
    asm("mov.b64 {%0, %1}, %2;" : "=f"(lo), "=f"(hi) : "l"(v));
}
__device__ __forceinline__ u64 ffma2(u64 a, u64 b, u64 c) {
    u64 d; asm("fma.rn.f32x2 %0, %1, %2, %3;" : "=l"(d) : "l"(a), "l"(b), "l"(c)); return d;
}

// ---------- 4-qubit circuit (identical math to passing kernels) ----------
template<int STRIDE>
__device__ __forceinline__ void apply_ry_s(float st[16], float c, float s) {
#pragma unroll
    for (int base = 0; base < 16; base += 2 * STRIDE) {
#pragma unroll
        for (int i = 0; i < STRIDE; i++) {
            float a0 = st[base + i];
            float a1 = st[base + i + STRIDE];
            st[base + i]          = c * a0 - s * a1;
            st[base + i + STRIDE] = s * a0 + c * a1;
        }
    }
}
__device__ __forceinline__ void cnot01(float st[16]) {
#pragma unroll
    for (int i = 0; i < 4; i++) { float t = st[8 + i]; st[8 + i] = st[12 + i]; st[12 + i] = t; }
}
__device__ __forceinline__ void cnot23(float st[16]) {
#pragma unroll
    for (int b = 0; b < 16; b += 4) { float t = st[b + 2]; st[b + 2] = st[b + 3]; st[b + 3] = t; }
}
__device__ __forceinline__ void cnot12(float st[16]) {
#pragma unroll
    for (int q0 = 0; q0 < 2; q0++)
#pragma unroll
        for (int q3 = 0; q3 < 2; q3++) {
            int b = q0 * 8 + 4 + q3;
            float t = st[b]; st[b] = st[b + 2]; st[b + 2] = t;
        }
}

__global__ __launch_bounds__(64, 8)
void dqn_fused_kernel(const float* __restrict__ X,      // [B,512]
                      const float* __restrict__ Wpre,   // [4,512]
                      const float* __restrict__ bpre,   // [4]
                      const float* __restrict__ qp,     // [24]
                      const float* __restrict__ Wpost,  // [200,4]
                      const float* __restrict__ bpost,  // [200]
                      float* __restrict__ out,          // [B,200]
                      int B)
{
    // layer-angle cos/sin (uniform across samples): accurate sincosf, once per block
    __shared__ float lc[24], ls[24], sb[4];
    const int tid = threadIdx.x;
    if (tid < 24) {
        float s, c;
        sincosf(qp[tid] * 0.5f, &s, &c);
        lc[tid] = c; ls[tid] = s;
    }
    if (tid < 4) sb[tid] = bpre[tid];
    __syncthreads();

    const int lane = tid & 31;
    const int warp = tid >> 5;
    const int group = blockIdx.x * 2 + warp;    // one warp per 32 samples, 2 warps/block
    const int base = group * 32;
    if (base >= B) return;

    // ---- Phase 1: pre = X @ Wpre.T (warp-cooperative, lane ends owning sample==lane)
    // W_pre in registers: lane covers columns {lane*4 + 128*j + 0..3}, j=0..3
    float4 w[4][4];
#pragma unroll
    for (int q = 0; q < 4; q++)
#pragma unroll
        for (int j = 0; j < 4; j++)
            w[q][j] = *(const float4*)(Wpre + q * 512 + j * 128 + lane * 4);

    float pre0 = 0.f, pre1 = 0.f, pre2 = 0.f, pre3 = 0.f;
    const bool o0 = (lane & 1) != 0;
    const bool o1 = (lane & 2) != 0;

#pragma unroll 4
    for (int s = 0; s < 32; s++) {
        const float* row = X + (size_t)(base + s) * 512 + lane * 4;
        float a0 = 0.f, a1 = 0.f, a2 = 0.f, a3 = 0.f;
#pragma unroll
        for (int j = 0; j < 4; j++) {
            float4 xv = *(const float4*)(row + j * 128);
            a0 += xv.x * w[0][j].x + xv.y * w[0][j].y + xv.z * w[0][j].z + xv.w * w[0][j].w;
            a1 += xv.x * w[1][j].x + xv.y * w[1][j].y + xv.z * w[1][j].z + xv.w * w[1][j].w;
            a2 += xv.x * w[2][j].x + xv.y * w[2][j].y + xv.z * w[2][j].z + xv.w * w[2][j].w;
            a3 += xv.x * w[3][j].x + xv.y * w[3][j].y + xv.z * w[3][j].z + xv.w * w[3][j].w;
        }
        // fold q-accumulators onto lane bits 0-1 (3 shfl), then xor-reduce (3 shfl)
        float s01 = o0 ? a0 : a1;
        float r01 = __shfl_xor_sync(FULL_MASK, s01, 1);
        float v01 = (o0 ? a1 : a0) + r01;        // pair-sum of q(bit0)
        float s23 = o0 ? a2 : a3;
        float r23 = __shfl_xor_sync(FULL_MASK, s23, 1);
        float v23 = (o0 ? a3 : a2) + r23;
        float s2  = o1 ? v01 : v23;
        float r2  = __shfl_xor_sync(FULL_MASK, s2, 2);
        float v   = (o1 ? v23 : v01) + r2;       // lane L: group-of-4 partial for q = L&3
        v += __shfl_xor_sync(FULL_MASK, v, 4);
        v += __shfl_xor_sync(FULL_MASK, v, 8);
        v += __shfl_xor_sync(FULL_MASK, v, 16);  // lane L: full pre_{L&3} for sample s
        float p0 = __shfl_sync(FULL_MASK, v, 0);
        float p1 = __shfl_sync(FULL_MASK, v, 1);
        float p2 = __shfl_sync(FULL_MASK, v, 2);
        float p3 = __shfl_sync(FULL_MASK, v, 3);
        if (lane == s) { pre0 = p0; pre1 = p1; pre2 = p2; pre3 = p3; }
    }

    // ---- Phase 2: per-lane 4-qubit circuit (lane == its sample), regs only ----
    float st[16];
#pragma unroll
    for (int i = 0; i < 16; i++) st[i] = 0.25f;
    {
        const float PI_4 = 0.78539816339744830962f;
        float h, c, s;
        h = tanhf(pre0 + sb[0]) * PI_4; c = __cosf(h); s = __sinf(h); apply_ry_s<8>(st, c, s);
        h = tanhf(pre1 + sb[1]) * PI_4; c = __cosf(h); s = __sinf(h); apply_ry_s<4>(st, c, s);
        h = tanhf(pre2 + sb[2]) * PI_4; c = __cosf(h); s = __sinf(h); apply_ry_s<2>(st, c, s);
        h = tanhf(pre3 + sb[3]) * PI_4; c = __cosf(h); s = __sinf(h); apply_ry_s<1>(st, c, s);
    }
#pragma unroll
    for (int k = 0; k < 6; k++) {
        cnot01(st); cnot23(st); cnot12(st);
        apply_ry_s<8>(st, lc[k * 4 + 0], ls[k * 4 + 0]);
        apply_ry_s<4>(st, lc[k * 4 + 1], ls[k * 4 + 1]);
        apply_ry_s<2>(st, lc[k * 4 + 2], ls[k * 4 + 2]);
        apply_ry_s<1>(st, lc[k * 4 + 3], ls[k * 4 + 3]);
    }
    float z0 = 0.f, z1 = 0.f, z2 = 0.f, z3 = 0.f;
#pragma unroll
    for (int i = 0; i < 16; i++) {
        float p = st[i] * st[i];
        z0 += (i & 8) ? -p : p;
        z1 += (i & 4) ? -p : p;
        z2 += (i & 2) ? -p : p;
        z3 += (i & 1) ? -p : p;
    }

    // ---- Phase 3: out = z @ Wpost.T + bpost, f32x2 column-pair FMAs (proven in R10) ----
    const int j0 = lane * 4;
    const int j1 = 128 + lane * 4;
    const bool second = (lane < 18);

    u64 c0[4], c1[4], d0[4], d1[4];
    u64 b01, b23, b45 = 0, b67 = 0;
    {
        float4 r0 = *(const float4*)(Wpost + (j0 + 0) * 4);
        float4 r1 = *(const float4*)(Wpost + (j0 + 1) * 4);
        float4 r2 = *(const float4*)(Wpost + (j0 + 2) * 4);
        float4 r3 = *(const float4*)(Wpost + (j0 + 3) * 4);
        c0[0] = f2pack(r0.x, r1.x); c0[1] = f2pack(r0.y, r1.y);
        c0[2] = f2pack(r0.z, r1.z); c0[3] = f2pack(r0.w, r1.w);
        c1[0] = f2pack(r2.x, r3.x); c1[1] = f2pack(r2.y, r3.y);
        c1[2] = f2pack(r2.z, r3.z); c1[3] = f2pack(r2.w, r3.w);
        float4 bp = *(const float4*)(bpost + j0);
        b01 = f2pack(bp.x, bp.y); b23 = f2pack(bp.z, bp.w);
    }
#pragma unroll
    for (int r = 0; r < 4; r++) { d0[r] = 0; d1[r] = 0; }
    if (second) {
        float4 r0 = *(const float4*)(Wpost + (j1 + 0) * 4);
        float4 r1 = *(const float4*)(Wpost + (j1 + 1) * 4);
        float4 r2 = *(const float4*)(Wpost + (j1 + 2) * 4);
        float4 r3 = *(const float4*)(Wpost + (j1 + 3) * 4);
        d0[0] = f2pack(r0.x, r1.x); d0[1] = f2pack(r0.y, r1.y);
        d0[2] = f2pack(r0.z, r1.z); d0[3] = f2pack(r0.w, r1.w);
        d1[0] = f2pack(r2.x, r3.x); d1[1] = f2pack(r2.y, r3.y);
        d1[2] = f2pack(r2.z, r3.z); d1[3] = f2pack(r2.w, r3.w);
        float4 bp = *(const float4*)(bpost + j1);
        b45 = f2pack(bp.x, bp.y); b67 = f2pack(bp.z, bp.w);
    }

#pragma unroll 4
    for (int s = 0; s < 32; s++) {
        float a0 = __shfl_sync(FULL_MASK, z0, s);
        float a1 = __shfl_sync(FULL_MASK, z1, s);
        float a2 = __shfl_sync(FULL_MASK, z2, s);
        float a3 = __shfl_sync(FULL_MASK, z3, s);
        u64 aa0 = f2pack(a0, a0), aa1 = f2pack(a1, a1);
        u64 aa2 = f2pack(a2, a2), aa3 = f2pack(a3, a3);
        float* orow = out + (size_t)(base + s) * 200;

        u64 r01 = ffma2(aa0, c0[0], b01);
        r01 = ffma2(aa1, c0[1], r01); r01 = ffma2(aa2, c0[2], r01); r01 = ffma2(aa3, c0[3], r01);
        u64 r23 = ffma2(aa0, c1[0], b23);
        r23 = ffma2(aa1, c1[1], r23); r23 = ffma2(aa2, c1[2], r23); r23 = ffma2(aa3, c1[3], r23);
        float4 o;
        f2unpack(r01, o.x, o.y); f2unpack(r23, o.z, o.w);
        *(float4*)(orow + j0) = o;

        if (second) {
            u64 r45 = ffma2(aa0, d0[0], b45);
            r45 = ffma2(aa1, d0[1], r45); r45 = ffma2(aa2, d0[2], r45); r45 = ffma2(aa3, d0[3], r45);
            u64 r67 = ffma2(aa0, d1[0], b67);
            r67 = ffma2(aa1, d1[1], r67); r67 = ffma2(aa2, d1[2], r67); r67 = ffma2(aa3, d1[3], r67);
            float4 p;
            f2unpack(r45, p.x, p.y); f2unpack(r67, p.z, p.w);
            *(float4*)(orow + j1) = p;
        }
    }
}

extern "C" void kernel_launch(void* const* d_in, const int* in_sizes, int n_in,
                              void* d_out, int out_size)
{
    const float* X     = (const float*)d_in[0];
    const float* Wpre  = (const float*)d_in[1];
    const float* bpre  = (const float*)d_in[2];
    const float* qp    = (const float*)d_in[3];
    const float* Wpost = (const float*)d_in[4];
    const float* bpost = (const float*)d_in[5];
    float* out = (float*)d_out;

    int B = in_sizes[0] / 512;            // 65536
    int groups = (B + 31) / 32;           // 2048 warps, one per 32 samples
    int blocks = (groups + 1) / 2;        // 2 warps (64 threads) per block -> 1024 blocks

    dqn_fused_kernel<<<blocks, 64>>>(X, Wpre, bpre, qp, Wpost, bpost, out, B);
}